// round 5
// baseline (speedup 1.0000x reference)
#include <cuda_runtime.h>
#include <mma.h>
#include <cstddef>

using namespace nvcuda;

#define BB      8
#define HH      56
#define WW      56
#define CC      192
#define HEADS   6
#define HEAD_DIM 32
#define NA      486
#define HW      3136
#define NROWS   25088
#define SCALE_F 0.17677669529663687f

// -------- scratch (device globals; allocation-free) --------
__device__ float g_v[(size_t)NROWS * CC];   // value projection [row][C]
__device__ float g_a[(size_t)NA * NROWS];   // attention logits TRANSPOSED [c][row]
__device__ float g_o[(size_t)NROWS * CC];   // pre-projection output [row][C]

// ============================================================
// TF32 WMMA GEMM: C[NROWS, NC] = A[NROWS,192] * B[192,NC] (+bias)
// Block 128x64, 256 threads (8 warps 2x4), warp tile 64x16.
// Double-buffered smem (1 sync/tile), tf32 conversion at smem store.
// TRANSC: write output column-major a_t[c][row] (for coalesced agg reads).
// SCALEOUT: multiply (acc+bias) by SCALE_F in epilogue.
// All smem strides are multiples of 4 floats (WMMA 16B ldm requirement).
// ============================================================
#define BM 128
#define BN 64
#define KB 32
#define A_LD 36   // 144B rows: 16B-multiple, bank-spread
#define B_LD 68   // 272B rows: 16B-multiple
#define C_LD 68   // MUST be 16B-multiple for store_matrix_sync
#define STG  (BM * A_LD + KB * B_LD)   // 6784 floats per stage

template<int NC, bool HASB, bool TRANSC, bool SCALEOUT>
__global__ void __launch_bounds__(256) gemm_tf32(const float* __restrict__ A,
                                                 const float* __restrict__ Bw,
                                                 const float* __restrict__ bias,
                                                 float* __restrict__ Cout)
{
    extern __shared__ float sm[];              // 2*STG floats (54.3 KB)

    const int tid = threadIdx.x;
    const int wid = tid >> 5;
    const int wm  = wid >> 2;                  // 0..1
    const int wn  = wid & 3;                   // 0..3
    const int rowBase = blockIdx.y * BM;
    const int colBase = blockIdx.x * BN;

    float4 ra[4];
    float4 rb[2];

    auto loadA = [&](int kt) {
#pragma unroll
        for (int p = 0; p < 4; p++) {
            int idx = tid + p * 256;
            int r  = idx >> 3;
            int c4 = (idx & 7) << 2;
            ra[p] = *(const float4*)&A[(size_t)(rowBase + r) * CC + kt + c4];
        }
    };
    auto loadB = [&](int kt) {
#pragma unroll
        for (int p = 0; p < 2; p++) {
            int idx = tid + p * 256;
            int k  = idx >> 4;
            int c4 = (idx & 15) << 2;
            int col = colBase + c4;
            const size_t base = (size_t)(kt + k) * NC + col;
            if ((NC & 3) == 0) {
                rb[p] = *(const float4*)&Bw[base];
            } else {
                // NC even -> element index even -> 8B-aligned float2 loads
                float4 v = make_float4(0.f, 0.f, 0.f, 0.f);
                if (col + 1 < NC) {
                    float2 lo = *(const float2*)&Bw[base];
                    v.x = lo.x; v.y = lo.y;
                    if (col + 3 < NC) {
                        float2 hi = *(const float2*)&Bw[base + 2];
                        v.z = hi.x; v.w = hi.y;
                    } else if (col + 2 < NC) {
                        v.z = Bw[base + 2];
                    }
                } else if (col < NC) {
                    v.x = Bw[base];
                }
                rb[p] = v;
            }
        }
    };
    auto cvt4 = [](float4& v) {
        v.x = wmma::__float_to_tf32(v.x);
        v.y = wmma::__float_to_tf32(v.y);
        v.z = wmma::__float_to_tf32(v.z);
        v.w = wmma::__float_to_tf32(v.w);
    };
    auto storeSmem = [&](int stage) {
        float* As = sm + stage * STG;
        float* Bs = As + BM * A_LD;
#pragma unroll
        for (int p = 0; p < 4; p++) {
            int idx = tid + p * 256;
            int r  = idx >> 3;
            int c4 = (idx & 7) << 2;
            cvt4(ra[p]);
            *(float4*)&As[r * A_LD + c4] = ra[p];
        }
#pragma unroll
        for (int p = 0; p < 2; p++) {
            int idx = tid + p * 256;
            int k  = idx >> 4;
            int c4 = (idx & 15) << 2;
            cvt4(rb[p]);
            *(float4*)&Bs[k * B_LD + c4] = rb[p];
        }
    };

    wmma::fragment<wmma::accumulator, 16, 16, 8, float> cf[4];
#pragma unroll
    for (int f = 0; f < 4; f++) wmma::fill_fragment(cf[f], 0.f);

    loadA(0); loadB(0);
    storeSmem(0);
    __syncthreads();

#pragma unroll 1
    for (int kt = 0; kt < CC; kt += KB) {
        const int cur = (kt / KB) & 1;
        const bool more = (kt + KB) < CC;
        if (more) { loadA(kt + KB); loadB(kt + KB); }

        const float* As = sm + cur * STG;
        const float* Bs = As + BM * A_LD;
#pragma unroll
        for (int kk = 0; kk < KB / 8; kk++) {
            wmma::fragment<wmma::matrix_b, 16, 16, 8, wmma::precision::tf32, wmma::row_major> bf;
            wmma::load_matrix_sync(bf, &Bs[(kk * 8) * B_LD + wn * 16], B_LD);
#pragma unroll
            for (int f = 0; f < 4; f++) {
                wmma::fragment<wmma::matrix_a, 16, 16, 8, wmma::precision::tf32, wmma::row_major> af;
                wmma::load_matrix_sync(af, &As[(wm * 64 + f * 16) * A_LD + kk * 8], A_LD);
                wmma::mma_sync(cf[f], af, bf, cf[f]);
            }
        }
        if (more) {
            storeSmem(cur ^ 1);
            __syncthreads();
        }
    }

    // epilogue: stage through smem, guarded write + bias
    __syncthreads();
    float* Cs = sm;                            // [BM][C_LD]
#pragma unroll
    for (int f = 0; f < 4; f++)
        wmma::store_matrix_sync(&Cs[(wm * 64 + f * 16) * C_LD + wn * 16], cf[f], C_LD,
                                wmma::mem_row_major);
    __syncthreads();

    if (TRANSC) {
        // column-major output: Cout[c][row], coalesced along rows
#pragma unroll
        for (int p = 0; p < (BM * BN) / 256; p++) {
            int idx = tid + p * 256;
            int c = idx >> 7;                  // 0..63
            int r = idx & 127;                 // 0..127
            int gc = colBase + c;
            if (gc < NC) {
                float v = Cs[r * C_LD + c];
                if (HASB) v += bias[gc];
                if (SCALEOUT) v *= SCALE_F;
                Cout[(size_t)gc * NROWS + rowBase + r] = v;
            }
        }
    } else {
#pragma unroll
        for (int p = 0; p < (BM * BN) / 256; p++) {
            int idx = tid + p * 256;
            int r = idx >> 6;
            int c = idx & 63;
            int gc = colBase + c;
            if (gc < NC) {
                float v = Cs[r * C_LD + c];
                if (HASB) v += bias[gc];
                if (SCALEOUT) v *= SCALE_F;
                Cout[(size_t)(rowBase + r) * NC + gc] = v;
            }
        }
    }
}

// ============================================================
// Fused softmax + attention-apply + fold.
// a is TRANSPOSED [c][row] and pre-scaled by SCALE_F, so every one
// of the 81 logit loads per thread is warp-coalesced (lanes = adjacent px).
// ============================================================
__global__ void agg_kernel(const float* __restrict__ a,
                           const float* __restrict__ v,
                           float* __restrict__ o)
{
    extern __shared__ float vsm[];   // 20*20 pixels, stride 33 (conflict-free)

    const int bh = blockIdx.z;
    const int b  = bh / HEADS;
    const int h  = bh - b * HEADS;
    const int ty0 = blockIdx.y * 16;
    const int tx0 = blockIdx.x * 16;
    const int tid = threadIdx.x;

    // cooperative load of v tile+halo for this head (zeros outside image)
    for (int i = tid; i < 20 * 20 * 8; i += 256) {
        const int p = i >> 3;
        const int q = (i & 7) << 2;
        const int sy = p / 20;
        const int sx = p - sy * 20;
        const int gy = ty0 + sy - 2;
        const int gx = tx0 + sx - 2;
        float4 val = make_float4(0.f, 0.f, 0.f, 0.f);
        if (gy >= 0 && gy < HH && gx >= 0 && gx < WW)
            val = *(const float4*)&v[((size_t)(b * HW + gy * WW + gx)) * CC + h * HEAD_DIM + q];
        float* d = &vsm[p * 33 + q];
        d[0] = val.x; d[1] = val.y; d[2] = val.z; d[3] = val.w;
    }
    __syncthreads();

    const int px = tid & 15;
    const int py = tid >> 4;
    const int gy = ty0 + py;
    const int gx = tx0 + px;
    if (gy >= HH || gx >= WW) return;

    // reduce 81 softmaxed logits into 25 positional weights
    float w[25];
#pragma unroll
    for (int i = 0; i < 25; i++) w[i] = 0.f;

#pragma unroll
    for (int i = 0; i < 3; i++) {
#pragma unroll
        for (int j = 0; j < 3; j++) {
            const int cy = gy + 1 - i;
            const int cx = gx + 1 - j;
            if (cy < 0 || cy >= HH || cx < 0 || cx >= WW) continue;
            const size_t row = (size_t)(b * HW + cy * WW + cx);
            const float* ap = a + (size_t)(h * 81 + (i * 3 + j) * 9) * NROWS + row;
            float e[9];
#pragma unroll
            for (int l = 0; l < 9; l++) e[l] = ap[(size_t)l * NROWS];
            float m = e[0];
#pragma unroll
            for (int l = 1; l < 9; l++) m = fmaxf(m, e[l]);
            float s = 0.f;
#pragma unroll
            for (int l = 0; l < 9; l++) { e[l] = __expf(e[l] - m); s += e[l]; }
            const float inv = 1.f / s;
#pragma unroll
            for (int li = 0; li < 3; li++) {
#pragma unroll
                for (int lj = 0; lj < 3; lj++) {
                    w[(li - i + 2) * 5 + (lj - j + 2)] += e[li * 3 + lj] * inv;
                }
            }
        }
    }

    // weighted 5x5 gather of v from smem
    float acc[HEAD_DIM];
#pragma unroll
    for (int d = 0; d < HEAD_DIM; d++) acc[d] = 0.f;

#pragma unroll
    for (int dy = 0; dy < 5; dy++) {
#pragma unroll
        for (int dx = 0; dx < 5; dx++) {
            const float wv = w[dy * 5 + dx];
            const float* vp = &vsm[((py + dy) * 20 + (px + dx)) * 33];
#pragma unroll
            for (int d = 0; d < HEAD_DIM; d++) acc[d] += wv * vp[d];
        }
    }

    float* op = o + ((size_t)(b * HW + gy * WW + gx)) * CC + h * HEAD_DIM;
#pragma unroll
    for (int d = 0; d < HEAD_DIM; d += 4) {
        *(float4*)&op[d] = make_float4(acc[d], acc[d + 1], acc[d + 2], acc[d + 3]);
    }
}

// ============================================================
extern "C" void kernel_launch(void* const* d_in, const int* in_sizes, int n_in,
                              void* d_out, int out_size)
{
    const float* x  = (const float*)d_in[0];
    const float* Wv = (const float*)d_in[1];
    const float* Wa = (const float*)d_in[2];
    const float* ba = (const float*)d_in[3];
    const float* Wp = (const float*)d_in[4];
    const float* bp = (const float*)d_in[5];
    float* out = (float*)d_out;

    float *vp, *ap, *op;
    cudaGetSymbolAddress((void**)&vp, g_v);
    cudaGetSymbolAddress((void**)&ap, g_a);
    cudaGetSymbolAddress((void**)&op, g_o);

    const int smem_gemm = 2 * STG * sizeof(float);        // 54.3 KB
    const int smem_agg  = 20 * 20 * 33 * sizeof(float);   // 52.8 KB
    cudaFuncSetAttribute((const void*)gemm_tf32<192, false, false, false>,
                         cudaFuncAttributeMaxDynamicSharedMemorySize, smem_gemm);
    cudaFuncSetAttribute((const void*)gemm_tf32<486, true, true, true>,
                         cudaFuncAttributeMaxDynamicSharedMemorySize, smem_gemm);
    cudaFuncSetAttribute((const void*)gemm_tf32<192, true, false, false>,
                         cudaFuncAttributeMaxDynamicSharedMemorySize, smem_gemm);
    cudaFuncSetAttribute((const void*)agg_kernel,
                         cudaFuncAttributeMaxDynamicSharedMemorySize, smem_agg);

    // 1) v = x @ Wv
    gemm_tf32<192, false, false, false><<<dim3(3, NROWS / BM), 256, smem_gemm>>>(x, Wv, nullptr, vp);
    // 2) a_t = transpose((x @ Wa + ba) * SCALE)   (column-major, pre-scaled)
    gemm_tf32<486, true, true, true><<<dim3(8, NROWS / BM), 256, smem_gemm>>>(x, Wa, ba, ap);
    // 3) fused softmax + attention-apply + fold
    agg_kernel<<<dim3(4, 4, BB * HEADS), 256, smem_agg>>>(ap, vp, op);
    // 4) out = o @ Wp + bp
    gemm_tf32<192, true, false, false><<<dim3(3, NROWS / BM), 256, smem_gemm>>>(op, Wp, bp, out);
}

// round 6
// speedup vs baseline: 1.5034x; 1.5034x over previous
#include <cuda_runtime.h>
#include <mma.h>
#include <cstddef>

using namespace nvcuda;

#define BB      8
#define HH      56
#define WW      56
#define CC      192
#define HEADS   6
#define HEAD_DIM 32
#define NA      486
#define HW      3136
#define NROWS   25088
#define SCALE_F 0.17677669529663687f

// -------- scratch (device globals; allocation-free) --------
__device__ float g_v[(size_t)NROWS * CC];   // value projection [row][C]
__device__ float g_a[(size_t)NA * NROWS];   // attention logits TRANSPOSED [c][row], pre-scaled
__device__ float g_o[(size_t)NROWS * CC];   // pre-projection output [row][C]

// ============================================================
// TF32 WMMA GEMM (R3 skeleton: STATIC 35KB smem, 2 syncs/tile).
// Block 128x64, 256 threads (8 warps 2x4), warp tile 64x16, K chunk 32.
// tf32 conversion happens ONCE at smem store (not per fragment).
// TRANSC: write output column-major Cout[c][row]; SCALEOUT: *SCALE_F.
// All smem strides are multiples of 4 floats (WMMA 16B ldm req).
// ============================================================
#define BM 128
#define BN 64
#define KB 32
#define A_LD 36   // 144B rows: 16B-multiple, bank-spread
#define B_LD 68   // 272B rows: 16B-multiple
#define C_LD 68   // 16B-multiple for store_matrix_sync

template<int NC, bool HASB, bool TRANSC, bool SCALEOUT>
__global__ void __launch_bounds__(256) gemm_tf32(const float* __restrict__ A,
                                                 const float* __restrict__ Bw,
                                                 const float* __restrict__ bias,
                                                 float* __restrict__ Cout)
{
    __shared__ float sm[BM * B_LD];            // 8704 floats (34.8KB); As+Bs, reused as Cs
    float* As = sm;                            // [BM][A_LD]
    float* Bs = sm + BM * A_LD;                // [KB][B_LD]

    const int tid = threadIdx.x;
    const int wid = tid >> 5;
    const int wm  = wid >> 2;                  // 0..1
    const int wn  = wid & 3;                   // 0..3
    const int rowBase = blockIdx.y * BM;
    const int colBase = blockIdx.x * BN;

    float4 ra[4];
    float4 rb[2];

    auto loadA = [&](int kt) {
#pragma unroll
        for (int p = 0; p < 4; p++) {
            int idx = tid + p * 256;
            int r  = idx >> 3;
            int c4 = (idx & 7) << 2;
            ra[p] = *(const float4*)&A[(size_t)(rowBase + r) * CC + kt + c4];
        }
    };
    auto loadB = [&](int kt) {
#pragma unroll
        for (int p = 0; p < 2; p++) {
            int idx = tid + p * 256;
            int k  = idx >> 4;
            int c4 = (idx & 15) << 2;
            int col = colBase + c4;
            const size_t base = (size_t)(kt + k) * NC + col;
            if ((NC & 3) == 0) {
                rb[p] = *(const float4*)&Bw[base];
            } else {
                // NC even -> element index even -> 8B-aligned float2 loads
                float4 v = make_float4(0.f, 0.f, 0.f, 0.f);
                if (col + 1 < NC) {
                    float2 lo = *(const float2*)&Bw[base];
                    v.x = lo.x; v.y = lo.y;
                    if (col + 3 < NC) {
                        float2 hi = *(const float2*)&Bw[base + 2];
                        v.z = hi.x; v.w = hi.y;
                    } else if (col + 2 < NC) {
                        v.z = Bw[base + 2];
                    }
                } else if (col < NC) {
                    v.x = Bw[base];
                }
                rb[p] = v;
            }
        }
    };
    auto cvt4 = [](float4& v) {
        v.x = wmma::__float_to_tf32(v.x);
        v.y = wmma::__float_to_tf32(v.y);
        v.z = wmma::__float_to_tf32(v.z);
        v.w = wmma::__float_to_tf32(v.w);
    };
    auto storeSmem = [&]() {
#pragma unroll
        for (int p = 0; p < 4; p++) {
            int idx = tid + p * 256;
            int r  = idx >> 3;
            int c4 = (idx & 7) << 2;
            cvt4(ra[p]);
            *(float4*)&As[r * A_LD + c4] = ra[p];
        }
#pragma unroll
        for (int p = 0; p < 2; p++) {
            int idx = tid + p * 256;
            int k  = idx >> 4;
            int c4 = (idx & 15) << 2;
            cvt4(rb[p]);
            *(float4*)&Bs[k * B_LD + c4] = rb[p];
        }
    };

    wmma::fragment<wmma::accumulator, 16, 16, 8, float> cf[4];
#pragma unroll
    for (int f = 0; f < 4; f++) wmma::fill_fragment(cf[f], 0.f);

    loadA(0); loadB(0);
    storeSmem();
    __syncthreads();

#pragma unroll 1
    for (int kt = 0; kt < CC; kt += KB) {
        const bool more = (kt + KB) < CC;
        if (more) { loadA(kt + KB); loadB(kt + KB); }

#pragma unroll
        for (int kk = 0; kk < KB / 8; kk++) {
            wmma::fragment<wmma::matrix_b, 16, 16, 8, wmma::precision::tf32, wmma::row_major> bf;
            wmma::load_matrix_sync(bf, &Bs[(kk * 8) * B_LD + wn * 16], B_LD);
#pragma unroll
            for (int f = 0; f < 4; f++) {
                wmma::fragment<wmma::matrix_a, 16, 16, 8, wmma::precision::tf32, wmma::row_major> af;
                wmma::load_matrix_sync(af, &As[(wm * 64 + f * 16) * A_LD + kk * 8], A_LD);
                wmma::mma_sync(cf[f], af, bf, cf[f]);
            }
        }
        __syncthreads();
        if (more) { storeSmem(); __syncthreads(); }
    }

    // epilogue: stage through smem (reuse), guarded write + bias (+scale)
    float* Cs = sm;                            // [BM][C_LD]
#pragma unroll
    for (int f = 0; f < 4; f++)
        wmma::store_matrix_sync(&Cs[(wm * 64 + f * 16) * C_LD + wn * 16], cf[f], C_LD,
                                wmma::mem_row_major);
    __syncthreads();

    if (TRANSC) {
        // column-major output: Cout[c][row], coalesced along rows
#pragma unroll
        for (int p = 0; p < (BM * BN) / 256; p++) {
            int idx = tid + p * 256;
            int c = idx >> 7;                  // 0..63
            int r = idx & 127;                 // 0..127
            int gc = colBase + c;
            if (gc < NC) {
                float v = Cs[r * C_LD + c];
                if (HASB) v += bias[gc];
                if (SCALEOUT) v *= SCALE_F;
                Cout[(size_t)gc * NROWS + rowBase + r] = v;
            }
        }
    } else {
#pragma unroll
        for (int p = 0; p < (BM * BN) / 256; p++) {
            int idx = tid + p * 256;
            int r = idx >> 6;
            int c = idx & 63;
            int gc = colBase + c;
            if (gc < NC) {
                float v = Cs[r * C_LD + c];
                if (HASB) v += bias[gc];
                if (SCALEOUT) v *= SCALE_F;
                Cout[(size_t)(rowBase + r) * NC + gc] = v;
            }
        }
    }
}

// ============================================================
// Fused softmax + attention-apply + fold.
// a is TRANSPOSED [c][row] and pre-scaled, so every one of the 81
// logit loads per thread is warp-coalesced (lanes = adjacent px).
// ============================================================
__global__ void agg_kernel(const float* __restrict__ a,
                           const float* __restrict__ v,
                           float* __restrict__ o)
{
    extern __shared__ float vsm[];   // 20*20 pixels, stride 33 (conflict-free)

    const int bh = blockIdx.z;
    const int b  = bh / HEADS;
    const int h  = bh - b * HEADS;
    const int ty0 = blockIdx.y * 16;
    const int tx0 = blockIdx.x * 16;
    const int tid = threadIdx.x;

    // cooperative load of v tile+halo for this head (zeros outside image)
    for (int i = tid; i < 20 * 20 * 8; i += 256) {
        const int p = i >> 3;
        const int q = (i & 7) << 2;
        const int sy = p / 20;
        const int sx = p - sy * 20;
        const int gy = ty0 + sy - 2;
        const int gx = tx0 + sx - 2;
        float4 val = make_float4(0.f, 0.f, 0.f, 0.f);
        if (gy >= 0 && gy < HH && gx >= 0 && gx < WW)
            val = *(const float4*)&v[((size_t)(b * HW + gy * WW + gx)) * CC + h * HEAD_DIM + q];
        float* d = &vsm[p * 33 + q];
        d[0] = val.x; d[1] = val.y; d[2] = val.z; d[3] = val.w;
    }
    __syncthreads();

    const int px = tid & 15;
    const int py = tid >> 4;
    const int gy = ty0 + py;
    const int gx = tx0 + px;
    if (gy >= HH || gx >= WW) return;

    // reduce 81 softmaxed logits into 25 positional weights
    float w[25];
#pragma unroll
    for (int i = 0; i < 25; i++) w[i] = 0.f;

#pragma unroll
    for (int i = 0; i < 3; i++) {
#pragma unroll
        for (int j = 0; j < 3; j++) {
            const int cy = gy + 1 - i;
            const int cx = gx + 1 - j;
            if (cy < 0 || cy >= HH || cx < 0 || cx >= WW) continue;
            const size_t row = (size_t)(b * HW + cy * WW + cx);
            const float* ap = a + (size_t)(h * 81 + (i * 3 + j) * 9) * NROWS + row;
            float e[9];
#pragma unroll
            for (int l = 0; l < 9; l++) e[l] = ap[(size_t)l * NROWS];
            float m = e[0];
#pragma unroll
            for (int l = 1; l < 9; l++) m = fmaxf(m, e[l]);
            float s = 0.f;
#pragma unroll
            for (int l = 0; l < 9; l++) { e[l] = __expf(e[l] - m); s += e[l]; }
            const float inv = 1.f / s;
#pragma unroll
            for (int li = 0; li < 3; li++) {
#pragma unroll
                for (int lj = 0; lj < 3; lj++) {
                    w[(li - i + 2) * 5 + (lj - j + 2)] += e[li * 3 + lj] * inv;
                }
            }
        }
    }

    // weighted 5x5 gather of v from smem
    float acc[HEAD_DIM];
#pragma unroll
    for (int d = 0; d < HEAD_DIM; d++) acc[d] = 0.f;

#pragma unroll
    for (int dy = 0; dy < 5; dy++) {
#pragma unroll
        for (int dx = 0; dx < 5; dx++) {
            const float wv = w[dy * 5 + dx];
            const float* vp = &vsm[((py + dy) * 20 + (px + dx)) * 33];
#pragma unroll
            for (int d = 0; d < HEAD_DIM; d++) acc[d] += wv * vp[d];
        }
    }

    float* op = o + ((size_t)(b * HW + gy * WW + gx)) * CC + h * HEAD_DIM;
#pragma unroll
    for (int d = 0; d < HEAD_DIM; d += 4) {
        *(float4*)&op[d] = make_float4(acc[d], acc[d + 1], acc[d + 2], acc[d + 3]);
    }
}

// ============================================================
extern "C" void kernel_launch(void* const* d_in, const int* in_sizes, int n_in,
                              void* d_out, int out_size)
{
    const float* x  = (const float*)d_in[0];
    const float* Wv = (const float*)d_in[1];
    const float* Wa = (const float*)d_in[2];
    const float* ba = (const float*)d_in[3];
    const float* Wp = (const float*)d_in[4];
    const float* bp = (const float*)d_in[5];
    float* out = (float*)d_out;

    float *vp, *ap, *op;
    cudaGetSymbolAddress((void**)&vp, g_v);
    cudaGetSymbolAddress((void**)&ap, g_a);
    cudaGetSymbolAddress((void**)&op, g_o);

    const int smem_agg = 20 * 20 * 33 * sizeof(float);   // 52.8 KB -> opt-in
    cudaFuncSetAttribute(agg_kernel, cudaFuncAttributeMaxDynamicSharedMemorySize, smem_agg);

    // 1) v = x @ Wv
    gemm_tf32<192, false, false, false><<<dim3(3, NROWS / BM), 256>>>(x, Wv, nullptr, vp);
    // 2) a_t = transpose((x @ Wa + ba) * SCALE)   (column-major, pre-scaled)
    gemm_tf32<486, true, true, true><<<dim3(8, NROWS / BM), 256>>>(x, Wa, ba, ap);
    // 3) fused softmax + attention-apply + fold
    agg_kernel<<<dim3(4, 4, BB * HEADS), 256, smem_agg>>>(ap, vp, op);
    // 4) out = o @ Wp + bp
    gemm_tf32<192, true, false, false><<<dim3(3, NROWS / BM), 256>>>(op, Wp, bp, out);
}

// round 7
// speedup vs baseline: 2.5480x; 1.6949x over previous
#include <cuda_runtime.h>
#include <cuda_fp16.h>
#include <mma.h>
#include <cstddef>

using namespace nvcuda;

#define BB      8
#define HH      56
#define WW      56
#define CC      192
#define HEADS   6
#define HEAD_DIM 32
#define NA      486
#define HW      3136
#define NROWS   25088
#define SCALE_F 0.17677669529663687f

// -------- scratch (device globals; allocation-free) --------
__device__ float g_v[(size_t)NROWS * CC];   // value projection [row][C]
__device__ float g_a[(size_t)NA * NROWS];   // attention logits TRANSPOSED [c][row], pre-scaled
__device__ float g_o[(size_t)NROWS * CC];   // pre-projection output [row][C]

// ============================================================
// FP16 WMMA GEMM: C[NROWS, NC] = A[NROWS,192] * B[192,NC] (+bias)
// fp16 has 10+1 mantissa bits == tf32, so accuracy matches tf32,
// but fragments load via ldmatrix (1 op vs 8 scalar LDS) and each
// mma does K=16. Block 128x64, 256 threads (8 warps 2x4),
// warp tile 64x16, K chunk 32, static smem, fp32 accumulate.
// TRANSC: write output column-major Cout[c][row]; SCALEOUT: *SCALE_F.
// ============================================================
#define BM 128
#define BN 64
#define KB 32
#define A_LDH 40   // halves; 80B rows: mult of 8 halves, odd mult of 16B
#define B_LDH 72   // halves; 144B rows: mult of 8 halves, odd mult of 16B
#define C_LD  68   // floats; 16B-multiple for store_matrix_sync
// smem sized by the fp32 epilogue tile (128*68 floats = 34.8KB);
// the fp16 staging tiles (14.8KB) alias the same storage.

template<int NC, bool HASB, bool TRANSC, bool SCALEOUT>
__global__ void __launch_bounds__(256) gemm_fp16(const float* __restrict__ A,
                                                 const float* __restrict__ Bw,
                                                 const float* __restrict__ bias,
                                                 float* __restrict__ Cout)
{
    __shared__ float smf[BM * C_LD];           // 34.8KB; union of staging + epilogue
    __half* As = (__half*)smf;                 // [BM][A_LDH]
    __half* Bs = As + BM * A_LDH;              // [KB][B_LDH]

    const int tid = threadIdx.x;
    const int wid = tid >> 5;
    const int wm  = wid >> 2;                  // 0..1
    const int wn  = wid & 3;                   // 0..3
    const int rowBase = blockIdx.y * BM;
    const int colBase = blockIdx.x * BN;

    float4 ra[4];
    float4 rb[2];

    auto loadA = [&](int kt) {
#pragma unroll
        for (int p = 0; p < 4; p++) {
            int idx = tid + p * 256;
            int r  = idx >> 3;
            int c4 = (idx & 7) << 2;
            ra[p] = *(const float4*)&A[(size_t)(rowBase + r) * CC + kt + c4];
        }
    };
    auto loadB = [&](int kt) {
#pragma unroll
        for (int p = 0; p < 2; p++) {
            int idx = tid + p * 256;
            int k  = idx >> 4;
            int c4 = (idx & 15) << 2;
            int col = colBase + c4;
            const size_t base = (size_t)(kt + k) * NC + col;
            if ((NC & 3) == 0) {
                rb[p] = *(const float4*)&Bw[base];
            } else {
                // NC even -> element index even -> 8B-aligned float2 loads
                float4 v = make_float4(0.f, 0.f, 0.f, 0.f);
                if (col + 1 < NC) {
                    float2 lo = *(const float2*)&Bw[base];
                    v.x = lo.x; v.y = lo.y;
                    if (col + 3 < NC) {
                        float2 hi = *(const float2*)&Bw[base + 2];
                        v.z = hi.x; v.w = hi.y;
                    } else if (col + 2 < NC) {
                        v.z = Bw[base + 2];
                    }
                } else if (col < NC) {
                    v.x = Bw[base];
                }
                rb[p] = v;
            }
        }
    };
    auto storeSmem = [&]() {
#pragma unroll
        for (int p = 0; p < 4; p++) {
            int idx = tid + p * 256;
            int r  = idx >> 3;
            int c4 = (idx & 7) << 2;
            __half2 h0 = __floats2half2_rn(ra[p].x, ra[p].y);
            __half2 h1 = __floats2half2_rn(ra[p].z, ra[p].w);
            __half2* d = (__half2*)&As[r * A_LDH + c4];
            d[0] = h0; d[1] = h1;
        }
#pragma unroll
        for (int p = 0; p < 2; p++) {
            int idx = tid + p * 256;
            int k  = idx >> 4;
            int c4 = (idx & 15) << 2;
            __half2 h0 = __floats2half2_rn(rb[p].x, rb[p].y);
            __half2 h1 = __floats2half2_rn(rb[p].z, rb[p].w);
            __half2* d = (__half2*)&Bs[k * B_LDH + c4];
            d[0] = h0; d[1] = h1;
        }
    };

    wmma::fragment<wmma::accumulator, 16, 16, 16, float> cf[4];
#pragma unroll
    for (int f = 0; f < 4; f++) wmma::fill_fragment(cf[f], 0.f);

    loadA(0); loadB(0);
    storeSmem();
    __syncthreads();

#pragma unroll 1
    for (int kt = 0; kt < CC; kt += KB) {
        const bool more = (kt + KB) < CC;
        if (more) { loadA(kt + KB); loadB(kt + KB); }

#pragma unroll
        for (int kk = 0; kk < KB / 16; kk++) {
            wmma::fragment<wmma::matrix_b, 16, 16, 16, __half, wmma::row_major> bf;
            wmma::load_matrix_sync(bf, &Bs[(kk * 16) * B_LDH + wn * 16], B_LDH);
#pragma unroll
            for (int f = 0; f < 4; f++) {
                wmma::fragment<wmma::matrix_a, 16, 16, 16, __half, wmma::row_major> af;
                wmma::load_matrix_sync(af, &As[(wm * 64 + f * 16) * A_LDH + kk * 16], A_LDH);
                wmma::mma_sync(cf[f], af, bf, cf[f]);
            }
        }
        __syncthreads();
        if (more) { storeSmem(); __syncthreads(); }
    }

    // epilogue: stage through smem (fp32), guarded write + bias (+scale)
    float* Cs = smf;                           // [BM][C_LD]
#pragma unroll
    for (int f = 0; f < 4; f++)
        wmma::store_matrix_sync(&Cs[(wm * 64 + f * 16) * C_LD + wn * 16], cf[f], C_LD,
                                wmma::mem_row_major);
    __syncthreads();

    if (TRANSC) {
        // column-major output: Cout[c][row], coalesced along rows
#pragma unroll
        for (int p = 0; p < (BM * BN) / 256; p++) {
            int idx = tid + p * 256;
            int c = idx >> 7;                  // 0..63
            int r = idx & 127;                 // 0..127
            int gc = colBase + c;
            if (gc < NC) {
                float v = Cs[r * C_LD + c];
                if (HASB) v += bias[gc];
                if (SCALEOUT) v *= SCALE_F;
                Cout[(size_t)gc * NROWS + rowBase + r] = v;
            }
        }
    } else {
#pragma unroll
        for (int p = 0; p < (BM * BN) / 256; p++) {
            int idx = tid + p * 256;
            int r = idx >> 6;
            int c = idx & 63;
            int gc = colBase + c;
            if (gc < NC) {
                float v = Cs[r * C_LD + c];
                if (HASB) v += bias[gc];
                if (SCALEOUT) v *= SCALE_F;
                Cout[(size_t)(rowBase + r) * NC + gc] = v;
            }
        }
    }
}

// ============================================================
// Fused softmax + attention-apply + fold.
// a is TRANSPOSED [c][row] and pre-scaled, so every one of the 81
// logit loads per thread is warp-coalesced (lanes = adjacent px).
// ============================================================
__global__ void agg_kernel(const float* __restrict__ a,
                           const float* __restrict__ v,
                           float* __restrict__ o)
{
    extern __shared__ float vsm[];   // 20*20 pixels, stride 33 (conflict-free)

    const int bh = blockIdx.z;
    const int b  = bh / HEADS;
    const int h  = bh - b * HEADS;
    const int ty0 = blockIdx.y * 16;
    const int tx0 = blockIdx.x * 16;
    const int tid = threadIdx.x;

    // cooperative load of v tile+halo for this head (zeros outside image)
    for (int i = tid; i < 20 * 20 * 8; i += 256) {
        const int p = i >> 3;
        const int q = (i & 7) << 2;
        const int sy = p / 20;
        const int sx = p - sy * 20;
        const int gy = ty0 + sy - 2;
        const int gx = tx0 + sx - 2;
        float4 val = make_float4(0.f, 0.f, 0.f, 0.f);
        if (gy >= 0 && gy < HH && gx >= 0 && gx < WW)
            val = *(const float4*)&v[((size_t)(b * HW + gy * WW + gx)) * CC + h * HEAD_DIM + q];
        float* d = &vsm[p * 33 + q];
        d[0] = val.x; d[1] = val.y; d[2] = val.z; d[3] = val.w;
    }
    __syncthreads();

    const int px = tid & 15;
    const int py = tid >> 4;
    const int gy = ty0 + py;
    const int gx = tx0 + px;
    if (gy >= HH || gx >= WW) return;

    // reduce 81 softmaxed logits into 25 positional weights
    float w[25];
#pragma unroll
    for (int i = 0; i < 25; i++) w[i] = 0.f;

#pragma unroll
    for (int i = 0; i < 3; i++) {
#pragma unroll
        for (int j = 0; j < 3; j++) {
            const int cy = gy + 1 - i;
            const int cx = gx + 1 - j;
            if (cy < 0 || cy >= HH || cx < 0 || cx >= WW) continue;
            const size_t row = (size_t)(b * HW + cy * WW + cx);
            const float* ap = a + (size_t)(h * 81 + (i * 3 + j) * 9) * NROWS + row;
            float e[9];
#pragma unroll
            for (int l = 0; l < 9; l++) e[l] = ap[(size_t)l * NROWS];
            float m = e[0];
#pragma unroll
            for (int l = 1; l < 9; l++) m = fmaxf(m, e[l]);
            float s = 0.f;
#pragma unroll
            for (int l = 0; l < 9; l++) { e[l] = __expf(e[l] - m); s += e[l]; }
            const float inv = 1.f / s;
#pragma unroll
            for (int li = 0; li < 3; li++) {
#pragma unroll
                for (int lj = 0; lj < 3; lj++) {
                    w[(li - i + 2) * 5 + (lj - j + 2)] += e[li * 3 + lj] * inv;
                }
            }
        }
    }

    // weighted 5x5 gather of v from smem
    float acc[HEAD_DIM];
#pragma unroll
    for (int d = 0; d < HEAD_DIM; d++) acc[d] = 0.f;

#pragma unroll
    for (int dy = 0; dy < 5; dy++) {
#pragma unroll
        for (int dx = 0; dx < 5; dx++) {
            const float wv = w[dy * 5 + dx];
            const float* vp = &vsm[((py + dy) * 20 + (px + dx)) * 33];
#pragma unroll
            for (int d = 0; d < HEAD_DIM; d++) acc[d] += wv * vp[d];
        }
    }

    float* op = o + ((size_t)(b * HW + gy * WW + gx)) * CC + h * HEAD_DIM;
#pragma unroll
    for (int d = 0; d < HEAD_DIM; d += 4) {
        *(float4*)&op[d] = make_float4(acc[d], acc[d + 1], acc[d + 2], acc[d + 3]);
    }
}

// ============================================================
extern "C" void kernel_launch(void* const* d_in, const int* in_sizes, int n_in,
                              void* d_out, int out_size)
{
    const float* x  = (const float*)d_in[0];
    const float* Wv = (const float*)d_in[1];
    const float* Wa = (const float*)d_in[2];
    const float* ba = (const float*)d_in[3];
    const float* Wp = (const float*)d_in[4];
    const float* bp = (const float*)d_in[5];
    float* out = (float*)d_out;

    float *vp, *ap, *op;
    cudaGetSymbolAddress((void**)&vp, g_v);
    cudaGetSymbolAddress((void**)&ap, g_a);
    cudaGetSymbolAddress((void**)&op, g_o);

    const int smem_agg = 20 * 20 * 33 * sizeof(float);   // 52.8 KB -> opt-in
    cudaFuncSetAttribute(agg_kernel, cudaFuncAttributeMaxDynamicSharedMemorySize, smem_agg);

    // 1) v = x @ Wv
    gemm_fp16<192, false, false, false><<<dim3(3, NROWS / BM), 256>>>(x, Wv, nullptr, vp);
    // 2) a_t = transpose((x @ Wa + ba) * SCALE)   (column-major, pre-scaled)
    gemm_fp16<486, true, true, true><<<dim3(8, NROWS / BM), 256>>>(x, Wa, ba, ap);
    // 3) fused softmax + attention-apply + fold
    agg_kernel<<<dim3(4, 4, BB * HEADS), 256, smem_agg>>>(ap, vp, op);
    // 4) out = o @ Wp + bp
    gemm_fp16<192, true, false, false><<<dim3(3, NROWS / BM), 256>>>(op, Wp, bp, out);
}

// round 8
// speedup vs baseline: 2.6663x; 1.0464x over previous
#include <cuda_runtime.h>
#include <cuda_fp16.h>
#include <mma.h>
#include <cstddef>
#include <cstdint>

using namespace nvcuda;

#define BB      8
#define HH      56
#define WW      56
#define CC      192
#define HEADS   6
#define HEAD_DIM 32
#define NA      486
#define NAPAD   512
#define HW      3136
#define NROWS   25088
#define SCALE_F 0.17677669529663687f

// -------- scratch (device globals; allocation-free) --------
__device__ __half g_x16[(size_t)NROWS * CC];    // x in fp16
__device__ __half g_wv16[CC * CC];
__device__ __half g_wa16[CC * NAPAD];           // Wa padded 486->512, zero-filled
__device__ __half g_wp16[CC * CC];
__device__ __half g_v16[(size_t)NROWS * CC];    // value projection (fp16)
__device__ float  g_a[(size_t)NA * NROWS];      // logits TRANSPOSED [c][row], pre-scaled (fp32)
__device__ __half g_o16[(size_t)NROWS * CC];    // pre-projection output (fp16)

// ============================================================
// one-time fp32 -> fp16 conversion kernels
// ============================================================
__global__ void cvt_f2h(const float* __restrict__ s, __half* __restrict__ d, int n4)
{
    int i = blockIdx.x * blockDim.x + threadIdx.x;
    if (i < n4) {
        float4 v = ((const float4*)s)[i];
        __half2* o = (__half2*)d + i * 2;
        o[0] = __floats2half2_rn(v.x, v.y);
        o[1] = __floats2half2_rn(v.z, v.w);
    }
}
__global__ void cvt_pad_wa(const float* __restrict__ s, __half* __restrict__ d)
{
    int i = blockIdx.x * blockDim.x + threadIdx.x;   // over 192*512
    if (i < CC * NAPAD) {
        int r = i >> 9, c = i & (NAPAD - 1);
        d[i] = (c < NA) ? __float2half(s[r * NA + c]) : __float2half(0.f);
    }
}

// ============================================================
// FP16 GEMM, cp.async double-buffered, zero in-loop conversion.
// C[NROWS, NC] = A16[NROWS,192] * B16[192,NCPAD] (+bias fp32)
// Block 128x64, 256 threads (8 warps 2x4), warp tile 64x16, K chunk 32.
// OUT16: write fp16 output (no bias/scale/trans). TRANSC: Cout[c][row].
// ============================================================
#define BM 128
#define BN 64
#define KB 32
#define A_LDH 40   // halves; 80B rows (odd mult of 16B -> conflict-free ldmatrix)
#define B_LDH 72   // halves; 144B rows
#define C_LD  68   // floats; 16B-multiple for store_matrix_sync
#define A_SZ (BM * A_LDH)        // 5120 halves
#define B_SZ (KB * B_LDH)        // 2304 halves
#define STG_H (A_SZ + B_SZ)      // 7424 halves per stage; 2 stages < 128*C_LD floats

__device__ __forceinline__ void cpa16(void* dst, const void* src)
{
    uint32_t d = (uint32_t)__cvta_generic_to_shared(dst);
    asm volatile("cp.async.cg.shared.global [%0], [%1], 16;\n" :: "r"(d), "l"(src));
}

template<int NCPAD, int NC, bool HASB, bool TRANSC, bool SCALEOUT, bool OUT16>
__global__ void __launch_bounds__(256) gemm_h(const __half* __restrict__ A,
                                              const __half* __restrict__ Bw,
                                              const float* __restrict__ bias,
                                              void* __restrict__ CoutV)
{
    __shared__ __align__(16) float smf[BM * C_LD];   // 34.8KB; staging + epilogue union
    __half* sh = (__half*)smf;

    const int tid = threadIdx.x;
    const int wid = tid >> 5;
    const int wm  = wid >> 2;                  // 0..1
    const int wn  = wid & 3;                   // 0..3
    const int rowBase = blockIdx.y * BM;
    const int colBase = blockIdx.x * BN;

    auto loadStage = [&](int s, int kt) {
        __half* As = sh + s * STG_H;
        __half* Bs = As + A_SZ;
#pragma unroll
        for (int p = 0; p < 2; p++) {
            int c = tid + p * 256;             // 0..511 chunks of 8 halves
            int r = c >> 2, off = (c & 3) << 3;
            cpa16(&As[r * A_LDH + off], &A[(size_t)(rowBase + r) * CC + kt + off]);
        }
        {
            int k = tid >> 3, off = (tid & 7) << 3;
            cpa16(&Bs[k * B_LDH + off], &Bw[(size_t)(kt + k) * NCPAD + colBase + off]);
        }
        asm volatile("cp.async.commit_group;\n");
    };

    wmma::fragment<wmma::accumulator, 16, 16, 16, float> cf[4];
#pragma unroll
    for (int f = 0; f < 4; f++) wmma::fill_fragment(cf[f], 0.f);

    loadStage(0, 0);

#pragma unroll 1
    for (int t = 0; t < CC / KB; t++) {
        if (t + 1 < CC / KB) {
            loadStage((t + 1) & 1, (t + 1) * KB);
            asm volatile("cp.async.wait_group 1;\n");
        } else {
            asm volatile("cp.async.wait_group 0;\n");
        }
        __syncthreads();

        const __half* As = sh + (t & 1) * STG_H;
        const __half* Bs = As + A_SZ;
#pragma unroll
        for (int kk = 0; kk < KB / 16; kk++) {
            wmma::fragment<wmma::matrix_b, 16, 16, 16, __half, wmma::row_major> bf;
            wmma::load_matrix_sync(bf, &Bs[(kk * 16) * B_LDH + wn * 16], B_LDH);
#pragma unroll
            for (int f = 0; f < 4; f++) {
                wmma::fragment<wmma::matrix_a, 16, 16, 16, __half, wmma::row_major> af;
                wmma::load_matrix_sync(af, &As[(wm * 64 + f * 16) * A_LDH + kk * 16], A_LDH);
                wmma::mma_sync(cf[f], af, bf, cf[f]);
            }
        }
        __syncthreads();   // stage (t&1) free for reuse at t+2; also guards epilogue aliasing
    }

    // epilogue: stage fp32 through smem, then write
    float* Cs = smf;                           // [BM][C_LD]
#pragma unroll
    for (int f = 0; f < 4; f++)
        wmma::store_matrix_sync(&Cs[(wm * 64 + f * 16) * C_LD + wn * 16], cf[f], C_LD,
                                wmma::mem_row_major);
    __syncthreads();

    if (OUT16) {
        // fp16 output, no bias/scale/trans, NC multiple of 64 (no guards)
        __half* Cout = (__half*)CoutV;
#pragma unroll
        for (int p = 0; p < (BM * BN) / 512; p++) {
            int idx = tid + p * 256;           // 0..4095 half2 slots
            int r  = idx >> 5;                 // 0..127
            int c2 = (idx & 31) << 1;          // 0..62
            __half2 hv = __floats2half2_rn(Cs[r * C_LD + c2], Cs[r * C_LD + c2 + 1]);
            *(__half2*)&Cout[(size_t)(rowBase + r) * NC + colBase + c2] = hv;
        }
    } else if (TRANSC) {
        float* Cout = (float*)CoutV;
#pragma unroll
        for (int p = 0; p < (BM * BN) / 256; p++) {
            int idx = tid + p * 256;
            int c = idx >> 7;                  // 0..63
            int r = idx & 127;                 // 0..127
            int gc = colBase + c;
            if (gc < NC) {
                float v = Cs[r * C_LD + c];
                if (HASB) v += bias[gc];
                if (SCALEOUT) v *= SCALE_F;
                Cout[(size_t)gc * NROWS + rowBase + r] = v;
            }
        }
    } else {
        float* Cout = (float*)CoutV;
#pragma unroll
        for (int p = 0; p < (BM * BN) / 256; p++) {
            int idx = tid + p * 256;
            int r = idx >> 6;
            int c = idx & 63;
            int gc = colBase + c;
            if (gc < NC) {
                float v = Cs[r * C_LD + c];
                if (HASB) v += bias[gc];
                if (SCALEOUT) v *= SCALE_F;
                Cout[(size_t)(rowBase + r) * NC + gc] = v;
            }
        }
    }
}

// ============================================================
// Fused softmax + attention-apply + fold.
// a is TRANSPOSED [c][row] pre-scaled fp32 (coalesced 81 loads/thread).
// v is fp16 (converted to fp32 in smem); o written fp16.
// ============================================================
__global__ void agg_kernel(const float* __restrict__ a,
                           const __half* __restrict__ v,
                           __half* __restrict__ o)
{
    extern __shared__ float vsm[];   // 20*20 pixels, stride 33 (conflict-free)

    const int bh = blockIdx.z;
    const int b  = bh / HEADS;
    const int h  = bh - b * HEADS;
    const int ty0 = blockIdx.y * 16;
    const int tx0 = blockIdx.x * 16;
    const int tid = threadIdx.x;

    // cooperative load of v tile+halo (fp16 -> fp32 smem), zeros outside image
    for (int i = tid; i < 20 * 20 * 4; i += 256) {
        const int p = i >> 2;
        const int q = (i & 3) << 3;            // 8 halves per chunk
        const int sy = p / 20;
        const int sx = p - sy * 20;
        const int gy = ty0 + sy - 2;
        const int gx = tx0 + sx - 2;
        float4 raw = make_float4(0.f, 0.f, 0.f, 0.f);
        if (gy >= 0 && gy < HH && gx >= 0 && gx < WW)
            raw = *(const float4*)&v[((size_t)(b * HW + gy * WW + gx)) * CC + h * HEAD_DIM + q];
        const __half2* hp = (const __half2*)&raw;
        float* d = &vsm[p * 33 + q];
#pragma unroll
        for (int u = 0; u < 4; u++) {
            float2 f = __half22float2(hp[u]);
            d[u * 2 + 0] = f.x;
            d[u * 2 + 1] = f.y;
        }
    }
    __syncthreads();

    const int px = tid & 15;
    const int py = tid >> 4;
    const int gy = ty0 + py;
    const int gx = tx0 + px;
    if (gy >= HH || gx >= WW) return;

    // reduce 81 softmaxed logits into 25 positional weights
    float w[25];
#pragma unroll
    for (int i = 0; i < 25; i++) w[i] = 0.f;

#pragma unroll
    for (int i = 0; i < 3; i++) {
#pragma unroll
        for (int j = 0; j < 3; j++) {
            const int cy = gy + 1 - i;
            const int cx = gx + 1 - j;
            if (cy < 0 || cy >= HH || cx < 0 || cx >= WW) continue;
            const size_t row = (size_t)(b * HW + cy * WW + cx);
            const float* ap = a + (size_t)(h * 81 + (i * 3 + j) * 9) * NROWS + row;
            float e[9];
#pragma unroll
            for (int l = 0; l < 9; l++) e[l] = ap[(size_t)l * NROWS];
            float m = e[0];
#pragma unroll
            for (int l = 1; l < 9; l++) m = fmaxf(m, e[l]);
            float s = 0.f;
#pragma unroll
            for (int l = 0; l < 9; l++) { e[l] = __expf(e[l] - m); s += e[l]; }
            const float inv = 1.f / s;
#pragma unroll
            for (int li = 0; li < 3; li++) {
#pragma unroll
                for (int lj = 0; lj < 3; lj++) {
                    w[(li - i + 2) * 5 + (lj - j + 2)] += e[li * 3 + lj] * inv;
                }
            }
        }
    }

    // weighted 5x5 gather of v from smem
    float acc[HEAD_DIM];
#pragma unroll
    for (int d = 0; d < HEAD_DIM; d++) acc[d] = 0.f;

#pragma unroll
    for (int dy = 0; dy < 5; dy++) {
#pragma unroll
        for (int dx = 0; dx < 5; dx++) {
            const float wv = w[dy * 5 + dx];
            const float* vp = &vsm[((py + dy) * 20 + (px + dx)) * 33];
#pragma unroll
            for (int d = 0; d < HEAD_DIM; d++) acc[d] += wv * vp[d];
        }
    }

    __half2* op = (__half2*)(o + ((size_t)(b * HW + gy * WW + gx)) * CC + h * HEAD_DIM);
#pragma unroll
    for (int d = 0; d < HEAD_DIM / 2; d++)
        op[d] = __floats2half2_rn(acc[2 * d], acc[2 * d + 1]);
}

// ============================================================
extern "C" void kernel_launch(void* const* d_in, const int* in_sizes, int n_in,
                              void* d_out, int out_size)
{
    const float* x  = (const float*)d_in[0];
    const float* Wv = (const float*)d_in[1];
    const float* Wa = (const float*)d_in[2];
    const float* ba = (const float*)d_in[3];
    const float* Wp = (const float*)d_in[4];
    const float* bp = (const float*)d_in[5];
    float* out = (float*)d_out;

    __half *x16, *wv16, *wa16, *wp16, *v16, *o16;
    float *ap;
    cudaGetSymbolAddress((void**)&x16,  g_x16);
    cudaGetSymbolAddress((void**)&wv16, g_wv16);
    cudaGetSymbolAddress((void**)&wa16, g_wa16);
    cudaGetSymbolAddress((void**)&wp16, g_wp16);
    cudaGetSymbolAddress((void**)&v16,  g_v16);
    cudaGetSymbolAddress((void**)&ap,   g_a);
    cudaGetSymbolAddress((void**)&o16,  g_o16);

    const int smem_agg = 20 * 20 * 33 * sizeof(float);   // 52.8 KB -> opt-in
    cudaFuncSetAttribute(agg_kernel, cudaFuncAttributeMaxDynamicSharedMemorySize, smem_agg);

    // 0) one-time fp16 conversions
    cvt_f2h<<<(NROWS * CC / 4 + 255) / 256, 256>>>(x, x16, NROWS * CC / 4);
    cvt_f2h<<<(CC * CC / 4 + 255) / 256, 256>>>(Wv, wv16, CC * CC / 4);
    cvt_f2h<<<(CC * CC / 4 + 255) / 256, 256>>>(Wp, wp16, CC * CC / 4);
    cvt_pad_wa<<<(CC * NAPAD + 255) / 256, 256>>>(Wa, wa16);

    // 1) v16 = x @ Wv   (fp16 out)
    gemm_h<192, 192, false, false, false, true>
        <<<dim3(3, NROWS / BM), 256>>>(x16, wv16, nullptr, v16);
    // 2) a_t = transpose((x @ Wa + ba) * SCALE)   (fp32, column-major)
    gemm_h<NAPAD, NA, true, true, true, false>
        <<<dim3(NAPAD / BN, NROWS / BM), 256>>>(x16, wa16, ba, ap);
    // 3) fused softmax + attention-apply + fold  (o in fp16)
    agg_kernel<<<dim3(4, 4, BB * HEADS), 256, smem_agg>>>(ap, v16, o16);
    // 4) out = o @ Wp + bp   (fp32 out)
    gemm_h<192, 192, true, false, false, false>
        <<<dim3(3, NROWS / BM), 256>>>(o16, wp16, bp, out);
}

// round 9
// speedup vs baseline: 2.6981x; 1.0119x over previous
#include <cuda_runtime.h>
#include <cuda_fp16.h>
#include <mma.h>
#include <cstddef>
#include <cstdint>

using namespace nvcuda;

#define BB      8
#define HH      56
#define WW      56
#define CC      192
#define HEADS   6
#define HEAD_DIM 32
#define NA      486
#define NAPAD   512
#define HW      3136
#define NROWS   25088
#define SCALE_F 0.17677669529663687f

// -------- scratch (device globals; allocation-free) --------
__device__ __half g_x16[(size_t)NROWS * CC];    // x in fp16
__device__ __half g_wv16[CC * CC];
__device__ __half g_wa16[CC * NAPAD];           // Wa padded 486->512, zero-filled
__device__ __half g_wp16[CC * CC];
__device__ __half g_v16[(size_t)NROWS * CC];    // value projection (fp16)
__device__ float  g_a[(size_t)NA * NROWS];      // logits TRANSPOSED [c][row], pre-scaled (fp32)
__device__ __half g_o16[(size_t)NROWS * CC];    // pre-projection output (fp16)

// ============================================================
// one-time fp32 -> fp16 conversion kernels (vectorized)
// ============================================================
__global__ void cvt_f2h(const float* __restrict__ s, __half* __restrict__ d, int n4)
{
    int i = blockIdx.x * blockDim.x + threadIdx.x;
    if (i < n4) {
        float4 v = ((const float4*)s)[i];
        __half2* o = (__half2*)d + i * 2;
        o[0] = __floats2half2_rn(v.x, v.y);
        o[1] = __floats2half2_rn(v.z, v.w);
    }
}
// Wa [192][486] fp32 -> [192][512] fp16 (zero-pad). half2 outputs, float2 inputs.
__global__ void cvt_pad_wa(const float* __restrict__ s, __half2* __restrict__ d)
{
    int i = blockIdx.x * blockDim.x + threadIdx.x;   // over 192*256 half2 outputs
    if (i < CC * (NAPAD / 2)) {
        int r  = i >> 8;
        int c2 = i & 255;
        __half2 hv = __half2half2(__float2half(0.f));
        if (c2 < NA / 2) {   // 243 full float2 pairs cover cols 0..485
            float2 f = *(const float2*)&s[(size_t)r * NA + c2 * 2];
            hv = __floats2half2_rn(f.x, f.y);
        }
        d[(size_t)r * (NAPAD / 2) + c2] = hv;
    }
}

// ============================================================
// FP16 GEMM, 3-stage cp.async pipeline, warp tile 32x32 (4x2 warps).
// C[NROWS, NC] = A16[NROWS,192] * B16[192,NCPAD] (+bias fp32)
// Block 128x64, 256 threads. OUT16: fp16 out. TRANSC: Cout[c][row].
// ============================================================
#define BM 128
#define BN 64
#define KB 32
#define NT (CC / KB)             // 6 K-tiles
#define A_LDH 40                 // halves; 80B rows (odd mult of 16B)
#define B_LDH 72                 // halves; 144B rows
#define C_LD  68                 // floats; 16B-multiple for store_matrix_sync
#define A_SZ (BM * A_LDH)        // 5120 halves
#define B_SZ (KB * B_LDH)        // 2304 halves
#define STG_H (A_SZ + B_SZ)      // 7424 halves per stage
#define SMEM_BYTES (3 * STG_H * 2 > BM * C_LD * 4 ? 3 * STG_H * 2 : BM * C_LD * 4)

__device__ __forceinline__ void cpa16(void* dst, const void* src)
{
    uint32_t d = (uint32_t)__cvta_generic_to_shared(dst);
    asm volatile("cp.async.cg.shared.global [%0], [%1], 16;\n" :: "r"(d), "l"(src));
}

template<int NCPAD, int NC, bool HASB, bool TRANSC, bool SCALEOUT, bool OUT16>
__global__ void __launch_bounds__(256) gemm_h(const __half* __restrict__ A,
                                              const __half* __restrict__ Bw,
                                              const float* __restrict__ bias,
                                              void* __restrict__ CoutV)
{
    __shared__ __align__(16) unsigned char smraw[SMEM_BYTES];   // 43.5KB: 3 stages / epilogue union
    __half* sh = (__half*)smraw;
    float* smf = (float*)smraw;

    const int tid = threadIdx.x;
    const int wid = tid >> 5;
    const int wm  = wid >> 1;                  // 0..3  (32-row slabs)
    const int wn  = wid & 1;                   // 0..1  (32-col slabs)
    const int rowBase = blockIdx.y * BM;
    const int colBase = blockIdx.x * BN;

    auto loadStage = [&](int s, int kt) {
        __half* As = sh + s * STG_H;
        __half* Bs = As + A_SZ;
#pragma unroll
        for (int p = 0; p < 2; p++) {
            int c = tid + p * 256;             // 0..511 chunks of 8 halves
            int r = c >> 2, off = (c & 3) << 3;
            cpa16(&As[r * A_LDH + off], &A[(size_t)(rowBase + r) * CC + kt + off]);
        }
        {
            int k = tid >> 3, off = (tid & 7) << 3;
            cpa16(&Bs[k * B_LDH + off], &Bw[(size_t)(kt + k) * NCPAD + colBase + off]);
        }
        asm volatile("cp.async.commit_group;\n");
    };

    wmma::fragment<wmma::accumulator, 16, 16, 16, float> cf[2][2];
#pragma unroll
    for (int i = 0; i < 2; i++)
#pragma unroll
        for (int j = 0; j < 2; j++) wmma::fill_fragment(cf[i][j], 0.f);

    loadStage(0, 0);
    loadStage(1, KB);

#pragma unroll
    for (int t = 0; t < NT; t++) {
        if (t + 2 < NT) {
            loadStage((t + 2) % 3, (t + 2) * KB);   // target stage was consumed at t-1
            asm volatile("cp.async.wait_group 2;\n");
        } else if (t + 1 < NT) {
            asm volatile("cp.async.wait_group 1;\n");
        } else {
            asm volatile("cp.async.wait_group 0;\n");
        }
        __syncthreads();

        const __half* As = sh + (t % 3) * STG_H;
        const __half* Bs = As + A_SZ;
#pragma unroll
        for (int kk = 0; kk < KB / 16; kk++) {
            wmma::fragment<wmma::matrix_b, 16, 16, 16, __half, wmma::row_major> bf[2];
            wmma::fragment<wmma::matrix_a, 16, 16, 16, __half, wmma::row_major> af[2];
#pragma unroll
            for (int j = 0; j < 2; j++)
                wmma::load_matrix_sync(bf[j], &Bs[(kk * 16) * B_LDH + wn * 32 + j * 16], B_LDH);
#pragma unroll
            for (int i = 0; i < 2; i++)
                wmma::load_matrix_sync(af[i], &As[(wm * 32 + i * 16) * A_LDH + kk * 16], A_LDH);
#pragma unroll
            for (int i = 0; i < 2; i++)
#pragma unroll
                for (int j = 0; j < 2; j++)
                    wmma::mma_sync(cf[i][j], af[i], bf[j], cf[i][j]);
        }
        __syncthreads();   // all reads of stage t done before t+1 writes stage (t+3)%3 == t%3
    }

    // epilogue: stage fp32 through smem, then write
    float* Cs = smf;                           // [BM][C_LD]
#pragma unroll
    for (int i = 0; i < 2; i++)
#pragma unroll
        for (int j = 0; j < 2; j++)
            wmma::store_matrix_sync(&Cs[(wm * 32 + i * 16) * C_LD + wn * 32 + j * 16],
                                    cf[i][j], C_LD, wmma::mem_row_major);
    __syncthreads();

    if (OUT16) {
        __half* Cout = (__half*)CoutV;
#pragma unroll
        for (int p = 0; p < (BM * BN) / 512; p++) {
            int idx = tid + p * 256;           // half2 slots
            int r  = idx >> 5;
            int c2 = (idx & 31) << 1;
            __half2 hv = __floats2half2_rn(Cs[r * C_LD + c2], Cs[r * C_LD + c2 + 1]);
            *(__half2*)&Cout[(size_t)(rowBase + r) * NC + colBase + c2] = hv;
        }
    } else if (TRANSC) {
        float* Cout = (float*)CoutV;
#pragma unroll
        for (int p = 0; p < (BM * BN) / 256; p++) {
            int idx = tid + p * 256;
            int c = idx >> 7;                  // 0..63
            int r = idx & 127;                 // 0..127
            int gc = colBase + c;
            if (gc < NC) {
                float v = Cs[r * C_LD + c];
                if (HASB) v += bias[gc];
                if (SCALEOUT) v *= SCALE_F;
                Cout[(size_t)gc * NROWS + rowBase + r] = v;
            }
        }
    } else {
        float* Cout = (float*)CoutV;
#pragma unroll
        for (int p = 0; p < (BM * BN) / 256; p++) {
            int idx = tid + p * 256;
            int r = idx >> 6;
            int c = idx & 63;
            int gc = colBase + c;
            if (gc < NC) {
                float v = Cs[r * C_LD + c];
                if (HASB) v += bias[gc];
                if (SCALEOUT) v *= SCALE_F;
                Cout[(size_t)(rowBase + r) * NC + gc] = v;
            }
        }
    }
}

// ============================================================
// Fused softmax + attention-apply + fold.
// a is TRANSPOSED [c][row] pre-scaled fp32 (coalesced 81 loads/thread).
// v is fp16 (converted to fp32 in smem); o written fp16.
// ============================================================
__global__ void agg_kernel(const float* __restrict__ a,
                           const __half* __restrict__ v,
                           __half* __restrict__ o)
{
    extern __shared__ float vsm[];   // 20*20 pixels, stride 33 (conflict-free)

    const int bh = blockIdx.z;
    const int b  = bh / HEADS;
    const int h  = bh - b * HEADS;
    const int ty0 = blockIdx.y * 16;
    const int tx0 = blockIdx.x * 16;
    const int tid = threadIdx.x;

    // cooperative load of v tile+halo (fp16 -> fp32 smem), zeros outside image
    for (int i = tid; i < 20 * 20 * 4; i += 256) {
        const int p = i >> 2;
        const int q = (i & 3) << 3;            // 8 halves per chunk
        const int sy = p / 20;
        const int sx = p - sy * 20;
        const int gy = ty0 + sy - 2;
        const int gx = tx0 + sx - 2;
        float4 raw = make_float4(0.f, 0.f, 0.f, 0.f);
        if (gy >= 0 && gy < HH && gx >= 0 && gx < WW)
            raw = *(const float4*)&v[((size_t)(b * HW + gy * WW + gx)) * CC + h * HEAD_DIM + q];
        const __half2* hp = (const __half2*)&raw;
        float* d = &vsm[p * 33 + q];
#pragma unroll
        for (int u = 0; u < 4; u++) {
            float2 f = __half22float2(hp[u]);
            d[u * 2 + 0] = f.x;
            d[u * 2 + 1] = f.y;
        }
    }
    __syncthreads();

    const int px = tid & 15;
    const int py = tid >> 4;
    const int gy = ty0 + py;
    const int gx = tx0 + px;
    if (gy >= HH || gx >= WW) return;

    // reduce 81 softmaxed logits into 25 positional weights
    float w[25];
#pragma unroll
    for (int i = 0; i < 25; i++) w[i] = 0.f;

#pragma unroll
    for (int i = 0; i < 3; i++) {
#pragma unroll
        for (int j = 0; j < 3; j++) {
            const int cy = gy + 1 - i;
            const int cx = gx + 1 - j;
            if (cy < 0 || cy >= HH || cx < 0 || cx >= WW) continue;
            const size_t row = (size_t)(b * HW + cy * WW + cx);
            const float* ap = a + (size_t)(h * 81 + (i * 3 + j) * 9) * NROWS + row;
            float e[9];
#pragma unroll
            for (int l = 0; l < 9; l++) e[l] = ap[(size_t)l * NROWS];
            float m = e[0];
#pragma unroll
            for (int l = 1; l < 9; l++) m = fmaxf(m, e[l]);
            float s = 0.f;
#pragma unroll
            for (int l = 0; l < 9; l++) { e[l] = __expf(e[l] - m); s += e[l]; }
            const float inv = 1.f / s;
#pragma unroll
            for (int li = 0; li < 3; li++) {
#pragma unroll
                for (int lj = 0; lj < 3; lj++) {
                    w[(li - i + 2) * 5 + (lj - j + 2)] += e[li * 3 + lj] * inv;
                }
            }
        }
    }

    // weighted 5x5 gather of v from smem
    float acc[HEAD_DIM];
#pragma unroll
    for (int d = 0; d < HEAD_DIM; d++) acc[d] = 0.f;

#pragma unroll
    for (int dy = 0; dy < 5; dy++) {
#pragma unroll
        for (int dx = 0; dx < 5; dx++) {
            const float wv = w[dy * 5 + dx];
            const float* vp = &vsm[((py + dy) * 20 + (px + dx)) * 33];
#pragma unroll
            for (int d = 0; d < HEAD_DIM; d++) acc[d] += wv * vp[d];
        }
    }

    __half2* op = (__half2*)(o + ((size_t)(b * HW + gy * WW + gx)) * CC + h * HEAD_DIM);
#pragma unroll
    for (int d = 0; d < HEAD_DIM / 2; d++)
        op[d] = __floats2half2_rn(acc[2 * d], acc[2 * d + 1]);
}

// ============================================================
extern "C" void kernel_launch(void* const* d_in, const int* in_sizes, int n_in,
                              void* d_out, int out_size)
{
    const float* x  = (const float*)d_in[0];
    const float* Wv = (const float*)d_in[1];
    const float* Wa = (const float*)d_in[2];
    const float* ba = (const float*)d_in[3];
    const float* Wp = (const float*)d_in[4];
    const float* bp = (const float*)d_in[5];
    float* out = (float*)d_out;

    __half *x16, *wv16, *wa16, *wp16, *v16, *o16;
    float *ap;
    cudaGetSymbolAddress((void**)&x16,  g_x16);
    cudaGetSymbolAddress((void**)&wv16, g_wv16);
    cudaGetSymbolAddress((void**)&wa16, g_wa16);
    cudaGetSymbolAddress((void**)&wp16, g_wp16);
    cudaGetSymbolAddress((void**)&v16,  g_v16);
    cudaGetSymbolAddress((void**)&ap,   g_a);
    cudaGetSymbolAddress((void**)&o16,  g_o16);

    const int smem_agg = 20 * 20 * 33 * sizeof(float);   // 52.8 KB -> opt-in
    cudaFuncSetAttribute(agg_kernel, cudaFuncAttributeMaxDynamicSharedMemorySize, smem_agg);

    // 0) one-time fp16 conversions
    cvt_f2h<<<(NROWS * CC / 4 + 255) / 256, 256>>>(x, x16, NROWS * CC / 4);
    cvt_f2h<<<(CC * CC / 4 + 255) / 256, 256>>>(Wv, wv16, CC * CC / 4);
    cvt_f2h<<<(CC * CC / 4 + 255) / 256, 256>>>(Wp, wp16, CC * CC / 4);
    cvt_pad_wa<<<(CC * NAPAD / 2 + 255) / 256, 256>>>(Wa, (__half2*)wa16);

    // 1) v16 = x @ Wv   (fp16 out)
    gemm_h<192, 192, false, false, false, true>
        <<<dim3(3, NROWS / BM), 256>>>(x16, wv16, nullptr, v16);
    // 2) a_t = transpose((x @ Wa + ba) * SCALE)   (fp32, column-major)
    gemm_h<NAPAD, NA, true, true, true, false>
        <<<dim3(NAPAD / BN, NROWS / BM), 256>>>(x16, wa16, ba, ap);
    // 3) fused softmax + attention-apply + fold  (o in fp16)
    agg_kernel<<<dim3(4, 4, BB * HEADS), 256, smem_agg>>>(ap, v16, o16);
    // 4) out = o @ Wp + bp   (fp32 out)
    gemm_h<192, 192, true, false, false, false>
        <<<dim3(3, NROWS / BM), 256>>>(o16, wp16, bp, out);
}

// round 10
// speedup vs baseline: 3.0811x; 1.1420x over previous
#include <cuda_runtime.h>
#include <cuda_fp16.h>
#include <mma.h>
#include <cstddef>
#include <cstdint>

using namespace nvcuda;

#define BB      8
#define HH      56
#define WW      56
#define CC      192
#define HEADS   6
#define HEAD_DIM 32
#define NA      486
#define NAPAD   512
#define HW      3136
#define NROWS   25088
#define SCALE_F 0.17677669529663687f

// -------- scratch (device globals; allocation-free) --------
__device__ __half g_x16[(size_t)NROWS * CC];    // x in fp16
__device__ __half g_wv16[CC * CC];
__device__ __half g_wa16[CC * NAPAD];           // Wa padded 486->512, zero-filled
__device__ __half g_wp16[CC * CC];
__device__ __half g_v16[(size_t)NROWS * CC];    // value projection (fp16)
__device__ float  g_a[(size_t)NA * NROWS];      // logits TRANSPOSED [c][row], pre-scaled (fp32)
__device__ __half g_o16[(size_t)NROWS * CC];    // pre-projection output (fp16)

// ============================================================
// conversion kernels
// ============================================================
__global__ void cvt_f2h(const float* __restrict__ s, __half* __restrict__ d, int n4)
{
    int i = blockIdx.x * blockDim.x + threadIdx.x;
    if (i < n4) {
        float4 v = ((const float4*)s)[i];
        __half2* o = (__half2*)d + i * 2;
        o[0] = __floats2half2_rn(v.x, v.y);
        o[1] = __floats2half2_rn(v.z, v.w);
    }
}
// ONE launch for all three weight tensors (Wv, Wp fp32->fp16; Wa fp32->fp16 pad 486->512)
#define WV4   (CC * CC / 4)          // 9216 float4 chunks
#define WA2   (CC * (NAPAD / 2))     // 49152 half2 outputs
__global__ void cvt_weights(const float* __restrict__ Wv, const float* __restrict__ Wp,
                            const float* __restrict__ Wa,
                            __half* __restrict__ wv16, __half* __restrict__ wp16,
                            __half2* __restrict__ wa16)
{
    int i = blockIdx.x * blockDim.x + threadIdx.x;
    if (i < 2 * WV4) {
        const float* s = (i < WV4) ? Wv : Wp;
        __half* d = (i < WV4) ? wv16 : wp16;
        int j = (i < WV4) ? i : i - WV4;
        float4 v = ((const float4*)s)[j];
        __half2* o = (__half2*)d + j * 2;
        o[0] = __floats2half2_rn(v.x, v.y);
        o[1] = __floats2half2_rn(v.z, v.w);
    } else if (i < 2 * WV4 + WA2) {
        int j  = i - 2 * WV4;
        int r  = j >> 8;
        int c2 = j & 255;
        __half2 hv = __half2half2(__float2half(0.f));
        if (c2 < NA / 2) {
            float2 f = *(const float2*)&Wa[(size_t)r * NA + c2 * 2];
            hv = __floats2half2_rn(f.x, f.y);
        }
        wa16[(size_t)r * (NAPAD / 2) + c2] = hv;
    }
}

// ============================================================
// FP16 GEMM, 3-stage cp.async pipeline, warp tile 32x32 (4x2 warps).
// C[NROWS, NC] = A16[NROWS,192] * B16[192,NCPAD] (+bias fp32)
// ============================================================
#define BM 128
#define BN 64
#define KB 32
#define NT (CC / KB)             // 6 K-tiles
#define A_LDH 40                 // halves; 80B rows (odd mult of 16B)
#define B_LDH 72                 // halves; 144B rows
#define C_LD  68                 // floats; 16B-multiple for store_matrix_sync
#define A_SZ (BM * A_LDH)
#define B_SZ (KB * B_LDH)
#define STG_H (A_SZ + B_SZ)
#define SMEM_BYTES (3 * STG_H * 2 > BM * C_LD * 4 ? 3 * STG_H * 2 : BM * C_LD * 4)

__device__ __forceinline__ void cpa16(void* dst, const void* src)
{
    uint32_t d = (uint32_t)__cvta_generic_to_shared(dst);
    asm volatile("cp.async.cg.shared.global [%0], [%1], 16;\n" :: "r"(d), "l"(src));
}

template<int NCPAD, int NC, bool HASB, bool TRANSC, bool SCALEOUT, bool OUT16>
__global__ void __launch_bounds__(256) gemm_h(const __half* __restrict__ A,
                                              const __half* __restrict__ Bw,
                                              const float* __restrict__ bias,
                                              void* __restrict__ CoutV)
{
    __shared__ __align__(16) unsigned char smraw[SMEM_BYTES];
    __half* sh = (__half*)smraw;
    float* smf = (float*)smraw;

    const int tid = threadIdx.x;
    const int wid = tid >> 5;
    const int wm  = wid >> 1;                  // 0..3
    const int wn  = wid & 1;                   // 0..1
    const int rowBase = blockIdx.y * BM;
    const int colBase = blockIdx.x * BN;

    auto loadStage = [&](int s, int kt) {
        __half* As = sh + s * STG_H;
        __half* Bs = As + A_SZ;
#pragma unroll
        for (int p = 0; p < 2; p++) {
            int c = tid + p * 256;
            int r = c >> 2, off = (c & 3) << 3;
            cpa16(&As[r * A_LDH + off], &A[(size_t)(rowBase + r) * CC + kt + off]);
        }
        {
            int k = tid >> 3, off = (tid & 7) << 3;
            cpa16(&Bs[k * B_LDH + off], &Bw[(size_t)(kt + k) * NCPAD + colBase + off]);
        }
        asm volatile("cp.async.commit_group;\n");
    };

    wmma::fragment<wmma::accumulator, 16, 16, 16, float> cf[2][2];
#pragma unroll
    for (int i = 0; i < 2; i++)
#pragma unroll
        for (int j = 0; j < 2; j++) wmma::fill_fragment(cf[i][j], 0.f);

    loadStage(0, 0);
    loadStage(1, KB);

#pragma unroll
    for (int t = 0; t < NT; t++) {
        if (t + 2 < NT) {
            loadStage((t + 2) % 3, (t + 2) * KB);
            asm volatile("cp.async.wait_group 2;\n");
        } else if (t + 1 < NT) {
            asm volatile("cp.async.wait_group 1;\n");
        } else {
            asm volatile("cp.async.wait_group 0;\n");
        }
        __syncthreads();

        const __half* As = sh + (t % 3) * STG_H;
        const __half* Bs = As + A_SZ;
#pragma unroll
        for (int kk = 0; kk < KB / 16; kk++) {
            wmma::fragment<wmma::matrix_b, 16, 16, 16, __half, wmma::row_major> bf[2];
            wmma::fragment<wmma::matrix_a, 16, 16, 16, __half, wmma::row_major> af[2];
#pragma unroll
            for (int j = 0; j < 2; j++)
                wmma::load_matrix_sync(bf[j], &Bs[(kk * 16) * B_LDH + wn * 32 + j * 16], B_LDH);
#pragma unroll
            for (int i = 0; i < 2; i++)
                wmma::load_matrix_sync(af[i], &As[(wm * 32 + i * 16) * A_LDH + kk * 16], A_LDH);
#pragma unroll
            for (int i = 0; i < 2; i++)
#pragma unroll
                for (int j = 0; j < 2; j++)
                    wmma::mma_sync(cf[i][j], af[i], bf[j], cf[i][j]);
        }
        __syncthreads();
    }

    float* Cs = smf;                           // [BM][C_LD]
#pragma unroll
    for (int i = 0; i < 2; i++)
#pragma unroll
        for (int j = 0; j < 2; j++)
            wmma::store_matrix_sync(&Cs[(wm * 32 + i * 16) * C_LD + wn * 32 + j * 16],
                                    cf[i][j], C_LD, wmma::mem_row_major);
    __syncthreads();

    if (OUT16) {
        __half* Cout = (__half*)CoutV;
#pragma unroll
        for (int p = 0; p < (BM * BN) / 512; p++) {
            int idx = tid + p * 256;
            int r  = idx >> 5;
            int c2 = (idx & 31) << 1;
            __half2 hv = __floats2half2_rn(Cs[r * C_LD + c2], Cs[r * C_LD + c2 + 1]);
            *(__half2*)&Cout[(size_t)(rowBase + r) * NC + colBase + c2] = hv;
        }
    } else if (TRANSC) {
        float* Cout = (float*)CoutV;
#pragma unroll
        for (int p = 0; p < (BM * BN) / 256; p++) {
            int idx = tid + p * 256;
            int c = idx >> 7;
            int r = idx & 127;
            int gc = colBase + c;
            if (gc < NC) {
                float v = Cs[r * C_LD + c];
                if (HASB) v += bias[gc];
                if (SCALEOUT) v *= SCALE_F;
                Cout[(size_t)gc * NROWS + rowBase + r] = v;
            }
        }
    } else {
        float* Cout = (float*)CoutV;
#pragma unroll
        for (int p = 0; p < (BM * BN) / 256; p++) {
            int idx = tid + p * 256;
            int r = idx >> 6;
            int c = idx & 63;
            int gc = colBase + c;
            if (gc < NC) {
                float v = Cs[r * C_LD + c];
                if (HASB) v += bias[gc];
                if (SCALEOUT) v *= SCALE_F;
                Cout[(size_t)(rowBase + r) * NC + gc] = v;
            }
        }
    }
}

// ============================================================
// Fused softmax + attention-apply + fold.
// a: TRANSPOSED [c][row] pre-scaled fp32 (81 coalesced loads/thread).
// v: fp16 -> fp32 smem tile, pixel stride 36 floats (144B = odd mult
// of 16B -> LDS.128 phase-conflict-free); gather vectorized float4.
// ============================================================
#define VST 36   // smem floats per pixel

__global__ void agg_kernel(const float* __restrict__ a,
                           const __half* __restrict__ v,
                           __half* __restrict__ o)
{
    extern __shared__ float vsm[];   // 20*20 pixels * VST

    const int bh = blockIdx.z;
    const int b  = bh / HEADS;
    const int h  = bh - b * HEADS;
    const int ty0 = blockIdx.y * 16;
    const int tx0 = blockIdx.x * 16;
    const int tid = threadIdx.x;

    // cooperative load of v tile+halo (fp16 -> fp32 smem), zeros outside image
    for (int i = tid; i < 20 * 20 * 4; i += 256) {
        const int p = i >> 2;
        const int q = (i & 3) << 3;            // 8 halves per chunk
        const int sy = p / 20;
        const int sx = p - sy * 20;
        const int gy = ty0 + sy - 2;
        const int gx = tx0 + sx - 2;
        float4 raw = make_float4(0.f, 0.f, 0.f, 0.f);
        if (gy >= 0 && gy < HH && gx >= 0 && gx < WW)
            raw = *(const float4*)&v[((size_t)(b * HW + gy * WW + gx)) * CC + h * HEAD_DIM + q];
        const __half2* hp = (const __half2*)&raw;
        float2 f0 = __half22float2(hp[0]);
        float2 f1 = __half22float2(hp[1]);
        float2 f2 = __half22float2(hp[2]);
        float2 f3 = __half22float2(hp[3]);
        float4* d = (float4*)&vsm[p * VST + q];
        d[0] = make_float4(f0.x, f0.y, f1.x, f1.y);
        d[1] = make_float4(f2.x, f2.y, f3.x, f3.y);
    }
    __syncthreads();

    const int px = tid & 15;
    const int py = tid >> 4;
    const int gy = ty0 + py;
    const int gx = tx0 + px;
    if (gy >= HH || gx >= WW) return;

    // reduce 81 softmaxed logits into 25 positional weights
    float w[25];
#pragma unroll
    for (int i = 0; i < 25; i++) w[i] = 0.f;

#pragma unroll
    for (int i = 0; i < 3; i++) {
#pragma unroll
        for (int j = 0; j < 3; j++) {
            const int cy = gy + 1 - i;
            const int cx = gx + 1 - j;
            if (cy < 0 || cy >= HH || cx < 0 || cx >= WW) continue;
            const size_t row = (size_t)(b * HW + cy * WW + cx);
            const float* ap = a + (size_t)(h * 81 + (i * 3 + j) * 9) * NROWS + row;
            float e[9];
#pragma unroll
            for (int l = 0; l < 9; l++) e[l] = ap[(size_t)l * NROWS];
            float m = e[0];
#pragma unroll
            for (int l = 1; l < 9; l++) m = fmaxf(m, e[l]);
            float s = 0.f;
#pragma unroll
            for (int l = 0; l < 9; l++) { e[l] = __expf(e[l] - m); s += e[l]; }
            const float inv = 1.f / s;
#pragma unroll
            for (int li = 0; li < 3; li++) {
#pragma unroll
                for (int lj = 0; lj < 3; lj++) {
                    w[(li - i + 2) * 5 + (lj - j + 2)] += e[li * 3 + lj] * inv;
                }
            }
        }
    }

    // weighted 5x5 gather of v from smem, float4-vectorized
    float4 acc[HEAD_DIM / 4];
#pragma unroll
    for (int u = 0; u < HEAD_DIM / 4; u++) acc[u] = make_float4(0.f, 0.f, 0.f, 0.f);

#pragma unroll
    for (int dy = 0; dy < 5; dy++) {
#pragma unroll
        for (int dx = 0; dx < 5; dx++) {
            const float wv = w[dy * 5 + dx];
            const float4* vp = (const float4*)&vsm[((py + dy) * 20 + (px + dx)) * VST];
#pragma unroll
            for (int u = 0; u < HEAD_DIM / 4; u++) {
                float4 t = vp[u];
                acc[u].x += wv * t.x;
                acc[u].y += wv * t.y;
                acc[u].z += wv * t.z;
                acc[u].w += wv * t.w;
            }
        }
    }

    __half2* op = (__half2*)(o + ((size_t)(b * HW + gy * WW + gx)) * CC + h * HEAD_DIM);
#pragma unroll
    for (int u = 0; u < HEAD_DIM / 4; u++) {
        op[u * 2 + 0] = __floats2half2_rn(acc[u].x, acc[u].y);
        op[u * 2 + 1] = __floats2half2_rn(acc[u].z, acc[u].w);
    }
}

// ============================================================
extern "C" void kernel_launch(void* const* d_in, const int* in_sizes, int n_in,
                              void* d_out, int out_size)
{
    const float* x  = (const float*)d_in[0];
    const float* Wv = (const float*)d_in[1];
    const float* Wa = (const float*)d_in[2];
    const float* ba = (const float*)d_in[3];
    const float* Wp = (const float*)d_in[4];
    const float* bp = (const float*)d_in[5];
    float* out = (float*)d_out;

    __half *x16, *wv16, *wa16, *wp16, *v16, *o16;
    float *ap;
    cudaGetSymbolAddress((void**)&x16,  g_x16);
    cudaGetSymbolAddress((void**)&wv16, g_wv16);
    cudaGetSymbolAddress((void**)&wa16, g_wa16);
    cudaGetSymbolAddress((void**)&wp16, g_wp16);
    cudaGetSymbolAddress((void**)&v16,  g_v16);
    cudaGetSymbolAddress((void**)&ap,   g_a);
    cudaGetSymbolAddress((void**)&o16,  g_o16);

    const int smem_agg = 20 * 20 * VST * sizeof(float);   // 57.6 KB -> opt-in
    cudaFuncSetAttribute(agg_kernel, cudaFuncAttributeMaxDynamicSharedMemorySize, smem_agg);

    // 0) conversions: x (big, BW-bound) + all weights in one launch
    cvt_f2h<<<(NROWS * CC / 4 + 255) / 256, 256>>>(x, x16, NROWS * CC / 4);
    cvt_weights<<<(2 * WV4 + WA2 + 255) / 256, 256>>>(Wv, Wp, Wa, wv16, wp16, (__half2*)wa16);

    // 1) v16 = x @ Wv   (fp16 out)
    gemm_h<192, 192, false, false, false, true>
        <<<dim3(3, NROWS / BM), 256>>>(x16, wv16, nullptr, v16);
    // 2) a_t = transpose((x @ Wa + ba) * SCALE)   (fp32, column-major)
    gemm_h<NAPAD, NA, true, true, true, false>
        <<<dim3(NAPAD / BN, NROWS / BM), 256>>>(x16, wa16, ba, ap);
    // 3) fused softmax + attention-apply + fold  (o in fp16)
    agg_kernel<<<dim3(4, 4, BB * HEADS), 256, smem_agg>>>(ap, v16, o16);
    // 4) out = o @ Wp + bp   (fp32 out)
    gemm_h<192, 192, true, false, false, false>
        <<<dim3(3, NROWS / BM), 256>>>(o16, wp16, bp, out);
}